// round 12
// baseline (speedup 1.0000x reference)
#include <cuda_runtime.h>

#define HW    2048
#define HW2   1024
#define MASK  2047
#define BATCH 4
#define SY    32
#define WPB   4
#define NSTRIP 36          // 36*60 = 2160 >= 2048; overlap strips rewrite identical wrapped values
#define NBY   (HW / SY)    // 64

// folded constants
#define C0f     0.3623577545f      // cos(1.2)
#define S0f     0.9320390860f      // sin(1.2)
#define S02f    1.8640781720f      // 2*sin(1.2)
#define C02f    0.7247155090f      // 2*cos(1.2)
#define EPBf    0.19245009f        // EB  * sqrt(KB),  KB = (DT/TAU)/dx^2
#define EPDf    0.0038490018f      // EBD * sqrt(KB)
#define PCCf    (-0.0057735027f)   // M6EBD * KA / sqrt(KB),  KA = (DT/TAU)/(2dx)^2
#define KTf     0.1111111111f      // DT/dx^2
#define KAPf    1.8f
#define DTTAUf  0.3333333333f
#define APIXf   0.2864788976f      // alpha/pi
#define PIO2f   1.5707963268f

// stage1: P1/P2 pre-scaled by KA, E2 pre-scaled by KB (via eps' = eps*sqrt(KB))
__device__ __forceinline__ void stage1(float L, float R, float dn, float up,
                                       float& P1, float& P2, float& E2)
{
    float dx  = R - L;
    float dy  = up - dn;
    float dx2 = dx * dx;
    float dy2 = dy * dy;
    float r2  = dx2 + dy2;
    float t1  = fmaf(-3.0f, dy2, dx2);       // dx^2 - 3 dy^2
    float t2  = fmaf( 3.0f, dx2, -dy2);      // 3 dx^2 - dy^2
    float a3  = dx * t1;                     // Re(z^3)
    float b3  = dy * t2;                     // Im(z^3)
    float Az  = fmaf(a3, a3, -(b3 * b3));    // Re(z^6)
    float Bh  = a3 * b3;                     // Im(z^6)/2
    float r6  = r2 * r2 * r2;
    float ir6 = __fdividef(1.0f, fmaxf(r6, 1e-30f));
    float u   = fmaf(Az, C0f,  (Bh * S02f)) * ir6;   // cos(6(theta-theta0))
    float v   = fmaf(Bh, C02f, -(Az * S0f)) * ir6;   // sin(6(theta-theta0))
    float ep  = fmaf(EPDf, u, EPBf);        // eps * sqrt(KB)
    float pc  = ep * (PCCf * v);            // eps*eps_deriv*KA
    P1 =  pc * dx;
    P2 = -pc * dy;
    E2 = ep * ep;
}

// atan for g in (0, 10]; 3-term odd minimax on [0,1] (err ~6e-4 rad)
__device__ __forceinline__ float atan_pos(float g)
{
    float inv = __fdividef(1.0f, g);
    float w   = fminf(g, inv);
    float w2  = w * w;
    float p   = fmaf(w2, 0.0793331f, -0.2886680f);
    p = fmaf(w2, p, 0.9953545f);
    p = p * w;
    return (g > 1.0f) ? (PIO2f - p) : p;
}

template<bool WRAP>
__device__ __forceinline__ void sweep_body(const float* __restrict__ phi,
                                           const float* __restrict__ tempr,
                                           float* __restrict__ out,
                                           int y0)
{
    const unsigned FULL = 0xffffffffu;
    const int lane  = threadIdx.x & 31;
    const int wid   = threadIdx.x >> 5;
    const int strip = blockIdx.x * WPB + wid;       // 0..35
    const int b     = blockIdx.z;
    const int lm    = lane - 1;
    const int lp    = lane + 1;

    const int xc = (strip * 60 - 2 + 2 * lane) & MASK;
    const size_t base = (size_t)b * HW * HW;
    const float2* __restrict__ pb = (const float2*)(phi   + base) + (xc >> 1);
    const float2* __restrict__ tb = (const float2*)(tempr + base) + (xc >> 1);
    float2* __restrict__ po = (float2*)(out + base) + (xc >> 1);
    float2* __restrict__ to = (float2*)(out + (size_t)BATCH * HW * HW + base) + (xc >> 1);

#define PROW(r) pb[((r) & MASK) * HW2]
#define TROW(r) tb[((r) & MASK) * HW2]

    // prologue (wrap-safe via mask; one-time). pm2 is transient.
    float2 pm2 = PROW(y0 - 2), pm1 = PROW(y0 - 1), p0 = PROW(y0);
    float2 pp1 = PROW(y0 + 1), pp2 = PROW(y0 + 2);
    float2 tm1 = TROW(y0 - 1), t0 = TROW(y0), tp1 = TROW(y0 + 1);

    float2 P1m, P1c, P2c, E2c;
    {
        float Lc = __shfl_sync(FULL, pm1.y, lm);
        float Rc = __shfl_sync(FULL, pm1.x, lp);
        float d0, d1;
        stage1(Lc,    pm1.y, pm2.x, p0.x, P1m.x, d0, d1);
        stage1(pm1.x, Rc,    pm2.y, p0.y, P1m.y, d0, d1);
    }
    {
        float Lc = __shfl_sync(FULL, p0.y, lm);
        float Rc = __shfl_sync(FULL, p0.x, lp);
        stage1(Lc,   p0.y, pm1.x, pp1.x, P1c.x, P2c.x, E2c.x);
        stage1(p0.x, Rc,   pm1.y, pp1.y, P1c.y, P2c.y, E2c.y);
    }

    const bool wr = (lane >= 1) && (lane <= 30);

    // marching pointers (interior path: no mask, no per-iter index math)
    const float2* pld = pb + (size_t)(y0 + 3) * HW2;
    const float2* tld = tb + (size_t)(y0 + 2) * HW2;
    float2* por = po + (size_t)y0 * HW2;
    float2* tor = to + (size_t)y0 * HW2;

    #pragma unroll 4
    for (int i = 0; i < SY; ++i) {
        float2 pnew, tnew;
        if (WRAP) {
            pnew = PROW(y0 + i + 3);
            tnew = TROW(y0 + i + 2);
        } else {
            pnew = *pld;  pld += HW2;
            tnew = *tld;  tld += HW2;
        }

        float2 P1n, P2n, E2n;
        {
            float Lc = __shfl_sync(FULL, pp1.y, lm);
            float Rc = __shfl_sync(FULL, pp1.x, lp);
            stage1(Lc,    pp1.y, p0.x, pp2.x, P1n.x, P2n.x, E2n.x);
            stage1(pp1.x, Rc,    p0.y, pp2.y, P1n.y, P2n.y, E2n.y);
        }

        float Lp  = __shfl_sync(FULL, p0.y,  lm);
        float Rp  = __shfl_sync(FULL, p0.x,  lp);
        float Lt  = __shfl_sync(FULL, t0.y,  lm);
        float Rt  = __shfl_sync(FULL, t0.x,  lp);
        float LP2 = __shfl_sync(FULL, P2c.y, lm);
        float RP2 = __shfl_sync(FULL, P2c.x, lp);

        float2 outp, outt;
        {   // column xc
            float lapp = (pp1.x + pm1.x) + (Lp + p0.y);
            lapp = fmaf(p0.x, -4.0f, lapp);
            float lapt = (tp1.x + tm1.x) + (Lt + t0.y);
            lapt = fmaf(t0.x, -4.0f, lapt);
            float term = (P1n.x - P1m.x) + (P2c.y - LP2);   // KA pre-folded
            float at   = atan_pos(fmaf(t0.x, -10.0f, 10.0f));
            float marg = fmaf(APIXf, at, p0.x - 0.5f);
            float q    = fmaf(-p0.x, p0.x, p0.x);
            float dphi = fmaf(E2c.x, lapp, term);           // KB pre-folded
            dphi = fmaf(q * marg, DTTAUf, dphi);
            outp.x = p0.x + dphi;
            outt.x = fmaf(KAPf, dphi, fmaf(KTf, lapt, t0.x));
        }
        {   // column xc+1
            float lapp = (pp1.y + pm1.y) + (p0.x + Rp);
            lapp = fmaf(p0.y, -4.0f, lapp);
            float lapt = (tp1.y + tm1.y) + (t0.x + Rt);
            lapt = fmaf(t0.y, -4.0f, lapt);
            float term = (P1n.y - P1m.y) + (RP2 - P2c.x);
            float at   = atan_pos(fmaf(t0.y, -10.0f, 10.0f));
            float marg = fmaf(APIXf, at, p0.y - 0.5f);
            float q    = fmaf(-p0.y, p0.y, p0.y);
            float dphi = fmaf(E2c.y, lapp, term);
            dphi = fmaf(q * marg, DTTAUf, dphi);
            outp.y = p0.y + dphi;
            outt.y = fmaf(KAPf, dphi, fmaf(KTf, lapt, t0.y));
        }

        if (wr) {
            __stcs(por, outp);      // streaming: outputs never re-read
            __stcs(tor, outt);
        }
        por += HW2;
        tor += HW2;

        pm1 = p0;  p0 = pp1;  pp1 = pp2;  pp2 = pnew;
        tm1 = t0;  t0 = tp1;  tp1 = tnew;
        P1m = P1c; P1c = P1n; P2c = P2n; E2c = E2n;
    }
#undef PROW
#undef TROW
}

__global__ __launch_bounds__(WPB * 32, 9)
void dendrite_sweep10(const float* __restrict__ phi,
                      const float* __restrict__ tempr,
                      float* __restrict__ out)
{
    const int by = blockIdx.y;
    const int y0 = by * SY;
    if (by == 0 || by == NBY - 1) {
        sweep_body<true>(phi, tempr, out, y0);
    } else {
        sweep_body<false>(phi, tempr, out, y0);
    }
}

extern "C" void kernel_launch(void* const* d_in, const int* in_sizes, int n_in,
                              void* d_out, int out_size)
{
    const float* phi   = (const float*)d_in[0];
    const float* tempr = (const float*)d_in[1];
    float* out = (float*)d_out;

    dim3 block(WPB * 32);
    dim3 grid(NSTRIP / WPB, NBY, BATCH);   // (9, 64, 4) = 2304 CTAs
    dendrite_sweep10<<<grid, block>>>(phi, tempr, out);
}

// round 13
// speedup vs baseline: 1.0979x; 1.0979x over previous
#include <cuda_runtime.h>

#define HW    2048
#define HW2   1024
#define MASK  2047
#define BATCH 4
#define SY    32
#define WPB   4
#define NSTRIP 36          // 36*60 = 2160 >= 2048; overlap strips rewrite identical wrapped values
#define NBY   (HW / SY)    // 64

// folded constants
#define C0f     0.3623577545f      // cos(1.2)
#define S0f     0.9320390860f      // sin(1.2)
#define S02f    1.8640781720f      // 2*sin(1.2)
#define C02f    0.7247155090f      // 2*cos(1.2)
#define EPBf    0.19245009f        // EB  * sqrt(KB),  KB = (DT/TAU)/dx^2
#define EPDf    0.0038490018f      // EBD * sqrt(KB)
#define PCCf    (-0.0057735027f)   // M6EBD * KA / sqrt(KB),  KA = (DT/TAU)/(2dx)^2
#define KTf     0.1111111111f      // DT/dx^2
#define KAPf    1.8f
#define DTTAUf  0.3333333333f
#define APIXf   0.2864788976f      // alpha/pi
#define PIO2f   1.5707963268f

// FMA-pipe reciprocal: exponent-magic seed + Newton (NO MUFU).
// seed rel err ~6%; 1 iter -> ~4e-3; 2 iters -> ~1e-5.
__device__ __forceinline__ float rcp_nr1(float a)
{
    float x = __uint_as_float(0x7EF311C3u - __float_as_uint(a));
    x = x * fmaf(-a, x, 2.0f);
    return x;
}
__device__ __forceinline__ float rcp_nr2(float a)
{
    float x = __uint_as_float(0x7EF311C3u - __float_as_uint(a));
    x = x * fmaf(-a, x, 2.0f);
    x = x * fmaf(-a, x, 2.0f);
    return x;
}

// stage1: P1/P2 pre-scaled by KA, E2 pre-scaled by KB (via eps' = eps*sqrt(KB))
__device__ __forceinline__ void stage1(float L, float R, float dn, float up,
                                       float& P1, float& P2, float& E2)
{
    float dx  = R - L;
    float dy  = up - dn;
    float dx2 = dx * dx;
    float dy2 = dy * dy;
    float r2  = dx2 + dy2;
    float t1  = fmaf(-3.0f, dy2, dx2);       // dx^2 - 3 dy^2
    float t2  = fmaf( 3.0f, dx2, -dy2);      // 3 dx^2 - dy^2
    float a3  = dx * t1;                     // Re(z^3)
    float b3  = dy * t2;                     // Im(z^3)
    float Az  = fmaf(a3, a3, -(b3 * b3));    // Re(z^6)
    float Bh  = a3 * b3;                     // Im(z^6)/2
    float r6  = r2 * r2 * r2;
    float ir6 = rcp_nr2(fmaxf(r6, 1e-30f));  // FMA-pipe reciprocal
    float u   = fmaf(Az, C0f,  (Bh * S02f)) * ir6;   // cos(6(theta-theta0))
    float v   = fmaf(Bh, C02f, -(Az * S0f)) * ir6;   // sin(6(theta-theta0))
    float ep  = fmaf(EPDf, u, EPBf);        // eps * sqrt(KB)
    float pc  = ep * (PCCf * v);            // eps*eps_deriv*KA
    P1 =  pc * dx;
    P2 = -pc * dy;
    E2 = ep * ep;
}

// atan for g in [0, 10]; 3-term odd minimax on [0,1] + reciprocal identity.
// reciprocal via 1-step Newton (err ~4e-3 rad total, inside the 1e-2 budget).
__device__ __forceinline__ float atan_pos(float g)
{
    float inv = rcp_nr1(g);
    float w   = fminf(g, inv);
    float w2  = w * w;
    float p   = fmaf(w2, 0.0793331f, -0.2886680f);
    p = fmaf(w2, p, 0.9953545f);
    p = p * w;
    return (g > 1.0f) ? (PIO2f - p) : p;
}

template<bool WRAP>
__device__ __forceinline__ void sweep_body(const float* __restrict__ phi,
                                           const float* __restrict__ tempr,
                                           float* __restrict__ out,
                                           int y0)
{
    const unsigned FULL = 0xffffffffu;
    const int lane  = threadIdx.x & 31;
    const int wid   = threadIdx.x >> 5;
    const int strip = blockIdx.x * WPB + wid;       // 0..35
    const int b     = blockIdx.z;
    const int lm    = lane - 1;
    const int lp    = lane + 1;

    const int xc = (strip * 60 - 2 + 2 * lane) & MASK;
    const size_t base = (size_t)b * HW * HW;
    const float2* __restrict__ pb = (const float2*)(phi   + base) + (xc >> 1);
    const float2* __restrict__ tb = (const float2*)(tempr + base) + (xc >> 1);
    float2* __restrict__ po = (float2*)(out + base) + (xc >> 1);
    float2* __restrict__ to = (float2*)(out + (size_t)BATCH * HW * HW + base) + (xc >> 1);

#define PROW(r) pb[((r) & MASK) * HW2]
#define TROW(r) tb[((r) & MASK) * HW2]

    // prologue (wrap-safe via mask; one-time). pm2 is transient.
    float2 pm2 = PROW(y0 - 2), pm1 = PROW(y0 - 1), p0 = PROW(y0);
    float2 pp1 = PROW(y0 + 1), pp2 = PROW(y0 + 2);
    float2 tm1 = TROW(y0 - 1), t0 = TROW(y0), tp1 = TROW(y0 + 1);

    float2 P1m, P1c, P2c, E2c;
    {
        float Lc = __shfl_sync(FULL, pm1.y, lm);
        float Rc = __shfl_sync(FULL, pm1.x, lp);
        float d0, d1;
        stage1(Lc,    pm1.y, pm2.x, p0.x, P1m.x, d0, d1);
        stage1(pm1.x, Rc,    pm2.y, p0.y, P1m.y, d0, d1);
    }
    {
        float Lc = __shfl_sync(FULL, p0.y, lm);
        float Rc = __shfl_sync(FULL, p0.x, lp);
        stage1(Lc,   p0.y, pm1.x, pp1.x, P1c.x, P2c.x, E2c.x);
        stage1(p0.x, Rc,   pm1.y, pp1.y, P1c.y, P2c.y, E2c.y);
    }

    const bool wr = (lane >= 1) && (lane <= 30);

    // marching pointers (interior path: no mask, no per-iter index math)
    const float2* pld = pb + (size_t)(y0 + 3) * HW2;
    const float2* tld = tb + (size_t)(y0 + 2) * HW2;
    float2* por = po + (size_t)y0 * HW2;
    float2* tor = to + (size_t)y0 * HW2;

    #pragma unroll 4
    for (int i = 0; i < SY; ++i) {
        float2 pnew, tnew;
        if (WRAP) {
            pnew = PROW(y0 + i + 3);
            tnew = TROW(y0 + i + 2);
        } else {
            pnew = *pld;  pld += HW2;
            tnew = *tld;  tld += HW2;
        }

        float2 P1n, P2n, E2n;
        {
            float Lc = __shfl_sync(FULL, pp1.y, lm);
            float Rc = __shfl_sync(FULL, pp1.x, lp);
            stage1(Lc,    pp1.y, p0.x, pp2.x, P1n.x, P2n.x, E2n.x);
            stage1(pp1.x, Rc,    p0.y, pp2.y, P1n.y, P2n.y, E2n.y);
        }

        float Lp  = __shfl_sync(FULL, p0.y,  lm);
        float Rp  = __shfl_sync(FULL, p0.x,  lp);
        float Lt  = __shfl_sync(FULL, t0.y,  lm);
        float Rt  = __shfl_sync(FULL, t0.x,  lp);
        float LP2 = __shfl_sync(FULL, P2c.y, lm);
        float RP2 = __shfl_sync(FULL, P2c.x, lp);

        float2 outp, outt;
        {   // column xc
            float lapp = (pp1.x + pm1.x) + (Lp + p0.y);
            lapp = fmaf(p0.x, -4.0f, lapp);
            float lapt = (tp1.x + tm1.x) + (Lt + t0.y);
            lapt = fmaf(t0.x, -4.0f, lapt);
            float term = (P1n.x - P1m.x) + (P2c.y - LP2);   // KA pre-folded
            float at   = atan_pos(fmaf(t0.x, -10.0f, 10.0f));
            float marg = fmaf(APIXf, at, p0.x - 0.5f);
            float q    = fmaf(-p0.x, p0.x, p0.x);
            float dphi = fmaf(E2c.x, lapp, term);           // KB pre-folded
            dphi = fmaf(q * marg, DTTAUf, dphi);
            outp.x = p0.x + dphi;
            outt.x = fmaf(KAPf, dphi, fmaf(KTf, lapt, t0.x));
        }
        {   // column xc+1
            float lapp = (pp1.y + pm1.y) + (p0.x + Rp);
            lapp = fmaf(p0.y, -4.0f, lapp);
            float lapt = (tp1.y + tm1.y) + (t0.x + Rt);
            lapt = fmaf(t0.y, -4.0f, lapt);
            float term = (P1n.y - P1m.y) + (RP2 - P2c.x);
            float at   = atan_pos(fmaf(t0.y, -10.0f, 10.0f));
            float marg = fmaf(APIXf, at, p0.y - 0.5f);
            float q    = fmaf(-p0.y, p0.y, p0.y);
            float dphi = fmaf(E2c.y, lapp, term);
            dphi = fmaf(q * marg, DTTAUf, dphi);
            outp.y = p0.y + dphi;
            outt.y = fmaf(KAPf, dphi, fmaf(KTf, lapt, t0.y));
        }

        if (wr) {
            __stcs(por, outp);      // streaming: outputs never re-read
            __stcs(tor, outt);
        }
        por += HW2;
        tor += HW2;

        pm1 = p0;  p0 = pp1;  pp1 = pp2;  pp2 = pnew;
        tm1 = t0;  t0 = tp1;  tp1 = tnew;
        P1m = P1c; P1c = P1n; P2c = P2n; E2c = E2n;
    }
#undef PROW
#undef TROW
}

__global__ __launch_bounds__(WPB * 32, 8)
void dendrite_sweep11(const float* __restrict__ phi,
                      const float* __restrict__ tempr,
                      float* __restrict__ out)
{
    const int by = blockIdx.y;
    const int y0 = by * SY;
    if (by == 0 || by == NBY - 1) {
        sweep_body<true>(phi, tempr, out, y0);
    } else {
        sweep_body<false>(phi, tempr, out, y0);
    }
}

extern "C" void kernel_launch(void* const* d_in, const int* in_sizes, int n_in,
                              void* d_out, int out_size)
{
    const float* phi   = (const float*)d_in[0];
    const float* tempr = (const float*)d_in[1];
    float* out = (float*)d_out;

    dim3 block(WPB * 32);
    dim3 grid(NSTRIP / WPB, NBY, BATCH);   // (9, 64, 4) = 2304 CTAs
    dendrite_sweep11<<<grid, block>>>(phi, tempr, out);
}

// round 15
// speedup vs baseline: 1.1032x; 1.0048x over previous
#include <cuda_runtime.h>

#define HW    2048
#define HW2   1024
#define MASK  2047
#define BATCH 4
#define SY    32
#define WPB   4
#define NSTRIP 36          // 36*60 = 2160 >= 2048; overlap strips rewrite identical wrapped values
#define NBY   (HW / SY)    // 64

// folded constants
#define C0f     0.3623577545f      // cos(1.2)
#define S0f     0.9320390860f      // sin(1.2)
#define S02f    1.8640781720f      // 2*sin(1.2)
#define C02f    0.7247155090f      // 2*cos(1.2)
#define EPBf    0.19245009f        // EB  * sqrt(KB),  KB = (DT/TAU)/dx^2
#define EPDf    0.0038490018f      // EBD * sqrt(KB)
#define PCCf    (-0.0057735027f)   // M6EBD * KA / sqrt(KB),  KA = (DT/TAU)/(2dx)^2
#define KTf     0.1111111111f      // DT/dx^2
#define KAPf    1.8f
#define DTTAUf  0.3333333333f
#define APIXf   0.2864788976f      // alpha/pi
#define PIO2f   1.5707963268f

// FMA-pipe reciprocal: exponent-magic seed + Newton (no MUFU)
__device__ __forceinline__ float rcp_nr1(float a)
{
    float x = __uint_as_float(0x7EF311C3u - __float_as_uint(a));
    x = x * fmaf(-a, x, 2.0f);
    return x;
}
__device__ __forceinline__ float rcp_nr2(float a)
{
    float x = __uint_as_float(0x7EF311C3u - __float_as_uint(a));
    x = x * fmaf(-a, x, 2.0f);
    x = x * fmaf(-a, x, 2.0f);
    return x;
}

// stage1: P1/P2 pre-scaled by KA, E2 pre-scaled by KB (via eps' = eps*sqrt(KB))
__device__ __forceinline__ void stage1(float L, float R, float dn, float up,
                                       float& P1, float& P2, float& E2)
{
    float dx  = R - L;
    float dy  = up - dn;
    float dx2 = dx * dx;
    float dy2 = dy * dy;
    float r2  = dx2 + dy2;
    float t1  = fmaf(-3.0f, dy2, dx2);       // dx^2 - 3 dy^2
    float t2  = fmaf( 3.0f, dx2, -dy2);      // 3 dx^2 - dy^2
    float a3  = dx * t1;                     // Re(z^3)
    float b3  = dy * t2;                     // Im(z^3)
    float Az  = fmaf(a3, a3, -(b3 * b3));    // Re(z^6)
    float Bh  = a3 * b3;                     // Im(z^6)/2
    float r6  = r2 * r2 * r2;
    float ir6 = rcp_nr2(fmaxf(r6, 1e-30f));
    float u   = fmaf(Az, C0f,  (Bh * S02f)) * ir6;   // cos(6(theta-theta0))
    float v   = fmaf(Bh, C02f, -(Az * S0f)) * ir6;   // sin(6(theta-theta0))
    float ep  = fmaf(EPDf, u, EPBf);        // eps * sqrt(KB)
    float pc  = ep * (PCCf * v);            // eps*eps_deriv*KA
    P1 =  pc * dx;
    P2 = -pc * dy;
    E2 = ep * ep;
}

// atan for g in [0,10]; 3-term odd minimax + 1-step-Newton reciprocal
__device__ __forceinline__ float atan_pos(float g)
{
    float inv = rcp_nr1(g);
    float w   = fminf(g, inv);
    float w2  = w * w;
    float p   = fmaf(w2, 0.0793331f, -0.2886680f);
    p = fmaf(w2, p, 0.9953545f);
    p = p * w;
    return (g > 1.0f) ? (PIO2f - p) : p;
}

// stage2 for one float2 column pair
__device__ __forceinline__ void stage2pair(const float2 pd, const float2 pc2, const float2 pu,
                                           float pL, float pR,
                                           const float2 td, const float2 tc, const float2 tu,
                                           float tL, float tR,
                                           const float2 P1u, const float2 P1d,
                                           const float2 P2, float QL, float QR,
                                           const float2 E2,
                                           float2& outp, float2& outt)
{
    {   // .x
        float lapp = (pu.x + pd.x) + (pL + pc2.y);
        lapp = fmaf(pc2.x, -4.0f, lapp);
        float lapt = (tu.x + td.x) + (tL + tc.y);
        lapt = fmaf(tc.x, -4.0f, lapt);
        float term = (P1u.x - P1d.x) + (P2.y - QL);
        float at   = atan_pos(fmaf(tc.x, -10.0f, 10.0f));
        float marg = fmaf(APIXf, at, pc2.x - 0.5f);
        float q    = fmaf(-pc2.x, pc2.x, pc2.x);
        float dphi = fmaf(E2.x, lapp, term);
        dphi = fmaf(q * marg, DTTAUf, dphi);
        outp.x = pc2.x + dphi;
        outt.x = fmaf(KAPf, dphi, fmaf(KTf, lapt, tc.x));
    }
    {   // .y
        float lapp = (pu.y + pd.y) + (pc2.x + pR);
        lapp = fmaf(pc2.y, -4.0f, lapp);
        float lapt = (tu.y + td.y) + (tc.x + tR);
        lapt = fmaf(tc.y, -4.0f, lapt);
        float term = (P1u.y - P1d.y) + (QR - P2.x);
        float at   = atan_pos(fmaf(tc.y, -10.0f, 10.0f));
        float marg = fmaf(APIXf, at, pc2.y - 0.5f);
        float q    = fmaf(-pc2.y, pc2.y, pc2.y);
        float dphi = fmaf(E2.y, lapp, term);
        dphi = fmaf(q * marg, DTTAUf, dphi);
        outp.y = pc2.y + dphi;
        outt.y = fmaf(KAPf, dphi, fmaf(KTf, lapt, tc.y));
    }
}

template<bool WRAP>
__device__ __forceinline__ void sweep_body(const float* __restrict__ phi,
                                           const float* __restrict__ tempr,
                                           float* __restrict__ out,
                                           int y0)
{
    const unsigned FULL = 0xffffffffu;
    const int lane  = threadIdx.x & 31;
    const int wid   = threadIdx.x >> 5;
    const int strip = blockIdx.x * WPB + wid;       // 0..35
    const int b     = blockIdx.z;
    const int lm    = lane - 1;
    const int lp    = lane + 1;

    const int xc = (strip * 60 - 2 + 2 * lane) & MASK;
    const size_t base = (size_t)b * HW * HW;
    const float2* __restrict__ pb = (const float2*)(phi   + base) + (xc >> 1);
    const float2* __restrict__ tb = (const float2*)(tempr + base) + (xc >> 1);
    float2* __restrict__ po = (float2*)(out + base) + (xc >> 1);
    float2* __restrict__ to = (float2*)(out + (size_t)BATCH * HW * HW + base) + (xc >> 1);

#define PROW(r) pb[((r) & MASK) * HW2]
#define TROW(r) tb[((r) & MASK) * HW2]

    // prologue (wrap-safe via mask; one-time)
    float2 pm2 = PROW(y0 - 2), pm1 = PROW(y0 - 1), p0 = PROW(y0);
    float2 pp1 = PROW(y0 + 1), pp2 = PROW(y0 + 2);
    float2 tm1 = TROW(y0 - 1), t0 = TROW(y0), tp1 = TROW(y0 + 1);

    float2 P1m, P1c, P2c, E2c;
    {
        float Lc = __shfl_sync(FULL, pm1.y, lm);
        float Rc = __shfl_sync(FULL, pm1.x, lp);
        float d0, d1;
        stage1(Lc,    pm1.y, pm2.x, p0.x, P1m.x, d0, d1);
        stage1(pm1.x, Rc,    pm2.y, p0.y, P1m.y, d0, d1);
    }
    float pLx = __shfl_sync(FULL, p0.y, lm);    // carried x-halo of current p0 row
    float pRx = __shfl_sync(FULL, p0.x, lp);
    stage1(pLx,  p0.y, pm1.x, pp1.x, P1c.x, P2c.x, E2c.x);
    stage1(p0.x, pRx,  pm1.y, pp1.y, P1c.y, P2c.y, E2c.y);

    const bool wr = (lane >= 1) && (lane <= 30);

    const float2* pld = pb + (size_t)(y0 + 3) * HW2;
    const float2* tld = tb + (size_t)(y0 + 2) * HW2;
    float2* por = po + (size_t)y0 * HW2;
    float2* tor = to + (size_t)y0 * HW2;

    #pragma unroll 4
    for (int i = 0; i < SY / 2; ++i) {
        const int y = y0 + 2 * i;
        float2 pn1, pn2, tn1, tn2;
        if (WRAP) {
            pn1 = PROW(y + 3);  pn2 = PROW(y + 4);
            tn1 = TROW(y + 2);  tn2 = TROW(y + 3);
        } else {
            pn1 = pld[0];  pn2 = pld[HW2];  pld += 2 * HW2;
            tn1 = tld[0];  tn2 = tld[HW2];  tld += 2 * HW2;
        }

        // stage1 at row y+1
        float Lc1 = __shfl_sync(FULL, pp1.y, lm);
        float Rc1 = __shfl_sync(FULL, pp1.x, lp);
        float2 P1a, P2a, E2a;
        stage1(Lc1,   pp1.y, p0.x, pp2.x, P1a.x, P2a.x, E2a.x);
        stage1(pp1.x, Rc1,   p0.y, pp2.y, P1a.y, P2a.y, E2a.y);

        // stage1 at row y+2
        float Lc2 = __shfl_sync(FULL, pp2.y, lm);
        float Rc2 = __shfl_sync(FULL, pp2.x, lp);
        float2 P1b, P2b, E2b;
        stage1(Lc2,   pp2.y, pp1.x, pn1.x, P1b.x, P2b.x, E2b.x);
        stage1(pp2.x, Rc2,   pp1.y, pn1.y, P1b.y, P2b.y, E2b.y);

        // stage2 at row y
        float Lt = __shfl_sync(FULL, t0.y,  lm);
        float Rt = __shfl_sync(FULL, t0.x,  lp);
        float LQ = __shfl_sync(FULL, P2c.y, lm);
        float RQ = __shfl_sync(FULL, P2c.x, lp);
        float2 outp0, outt0;
        stage2pair(pm1, p0, pp1, pLx, pRx,
                   tm1, t0, tp1, Lt, Rt,
                   P1a, P1m, P2c, LQ, RQ, E2c, outp0, outt0);

        // stage2 at row y+1  (p halos = Lc1/Rc1 from stage1 above)
        float Lt1 = __shfl_sync(FULL, tp1.y, lm);
        float Rt1 = __shfl_sync(FULL, tp1.x, lp);
        float LQ1 = __shfl_sync(FULL, P2a.y, lm);
        float RQ1 = __shfl_sync(FULL, P2a.x, lp);
        float2 outp1, outt1;
        stage2pair(p0, pp1, pp2, Lc1, Rc1,
                   t0, tp1, tn1, Lt1, Rt1,
                   P1b, P1c, P2a, LQ1, RQ1, E2a, outp1, outt1);

        if (wr) {
            __stcs(por,       outp0);
            __stcs(por + HW2, outp1);
            __stcs(tor,       outt0);
            __stcs(tor + HW2, outt1);
        }
        por += 2 * HW2;
        tor += 2 * HW2;

        // advance two rows
        pm1 = pp1;  p0 = pp2;  pp1 = pn1;  pp2 = pn2;
        tm1 = tp1;  t0 = tn1;  tp1 = tn2;
        P1m = P1a;  P1c = P1b; P2c = P2b;  E2c = E2b;
        pLx = Lc2;  pRx = Rc2;
    }
#undef PROW
#undef TROW
}

__global__ __launch_bounds__(WPB * 32, 7)
void dendrite_sweep12(const float* __restrict__ phi,
                      const float* __restrict__ tempr,
                      float* __restrict__ out)
{
    const int by = blockIdx.y;
    const int y0 = by * SY;
    if (by == 0 || by == NBY - 1) {
        sweep_body<true>(phi, tempr, out, y0);
    } else {
        sweep_body<false>(phi, tempr, out, y0);
    }
}

extern "C" void kernel_launch(void* const* d_in, const int* in_sizes, int n_in,
                              void* d_out, int out_size)
{
    const float* phi   = (const float*)d_in[0];
    const float* tempr = (const float*)d_in[1];
    float* out = (float*)d_out;

    dim3 block(WPB * 32);
    dim3 grid(NSTRIP / WPB, NBY, BATCH);   // (9, 64, 4) = 2304 CTAs
    dendrite_sweep12<<<grid, block>>>(phi, tempr, out);
}